// round 2
// baseline (speedup 1.0000x reference)
#include <cuda_runtime.h>
#include <stdint.h>

#define Nn 100000
#define Ee 3200000
#define Hc 256
#define Kc 264          // 256 + 8 (pe)
#define STRc 60
#define PEc 8
#define NBLK 98         // ceil(Nn/1024)

// ---------------- scratch (device globals: no allocation allowed) ----------------
__device__ float g_Abuf[(size_t)Nn * Kc];     // [x | pe] concatenated, row-major
__device__ float g_hs [(size_t)Nn * Hc];      // pre-scaled features (norm * h)
__device__ float g_hs2[(size_t)Nn * Hc];
__device__ float g_norm[Nn];
__device__ int   g_deg[Nn];
__device__ int   g_cursor[Nn];
__device__ int   g_rowptr[Nn + 1];
__device__ int   g_bsum[128];
__device__ int   g_colsorted[Ee];

// ---------------- small helpers: packed f32x2 FMA ----------------
__device__ __forceinline__ uint64_t pack2_dup(float a) {
    uint32_t u = __float_as_uint(a);
    uint64_t r;
    asm("mov.b64 %0, {%1, %1};" : "=l"(r) : "r"(u));
    return r;
}
__device__ __forceinline__ void fma2(uint64_t& d, uint64_t a, uint64_t b) {
    asm("fma.rn.f32x2 %0, %1, %2, %0;" : "+l"(d) : "l"(a), "l"(b));
}
__device__ __forceinline__ float2 unpack2(uint64_t v) {
    uint32_t lo, hi;
    asm("mov.b64 {%0, %1}, %2;" : "=r"(lo), "=r"(hi) : "l"(v));
    float2 r; r.x = __uint_as_float(lo); r.y = __uint_as_float(hi);
    return r;
}

// ---------------- CSR build ----------------
__global__ void k_zero() {
    int i = blockIdx.x * blockDim.x + threadIdx.x;
    if (i < Nn) { g_deg[i] = 0; g_cursor[i] = 0; }
}

__global__ void k_deg(const int* __restrict__ row) {
    int e = blockIdx.x * blockDim.x + threadIdx.x;
    if (e < Ee) atomicAdd(&g_deg[row[e]], 1);
}

// per-block exclusive scan of deg -> rowptr (partial), block totals -> g_bsum, plus norm
__global__ void k_scan1() {
    __shared__ int s[1024];
    int tid = threadIdx.x;
    int gi = blockIdx.x * 1024 + tid;
    int v = (gi < Nn) ? g_deg[gi] : 0;
    s[tid] = v;
    __syncthreads();
    for (int off = 1; off < 1024; off <<= 1) {
        int t = (tid >= off) ? s[tid - off] : 0;
        __syncthreads();
        s[tid] += t;
        __syncthreads();
    }
    if (gi < Nn) {
        g_rowptr[gi] = s[tid] - v;             // exclusive within block
        g_norm[gi]   = rsqrtf(1.0f + (float)v);
    }
    if (tid == 1023) g_bsum[blockIdx.x] = s[1023];
}

__global__ void k_scan2() {
    __shared__ int s[128];
    int tid = threadIdx.x;
    int v = (tid < NBLK) ? g_bsum[tid] : 0;
    s[tid] = v;
    __syncthreads();
    for (int off = 1; off < 128; off <<= 1) {
        int t = (tid >= off) ? s[tid - off] : 0;
        __syncthreads();
        s[tid] += t;
        __syncthreads();
    }
    g_bsum[tid] = s[tid] - v;                  // exclusive block offsets
}

__global__ void k_scan3() {
    int i = blockIdx.x * blockDim.x + threadIdx.x;
    if (i < Nn) g_rowptr[i] += g_bsum[i >> 10];
}

__global__ void k_scatter(const int* __restrict__ row, const int* __restrict__ col) {
    int e = blockIdx.x * blockDim.x + threadIdx.x;
    if (e < Ee) {
        int r = row[e];
        int p = atomicAdd(&g_cursor[r], 1);
        g_colsorted[g_rowptr[r] + p] = col[e];
    }
}

// ---------------- pos-embedding + x copy into Abuf ----------------
// one warp per node: copies x row (64 float4) and computes 8-wide pe
__global__ void k_pe(const float* __restrict__ x, const float* __restrict__ pos,
                     const float* __restrict__ lap, const float* __restrict__ Wp,
                     const float* __restrict__ bp) {
    __shared__ float sh[8][120];
    int w = threadIdx.x >> 5, lane = threadIdx.x & 31;
    int i = blockIdx.x * 8 + w;
    if (i >= Nn) return;
    const float4* xr = (const float4*)(x + (size_t)i * Hc);
    float4* ar = (float4*)(g_Abuf + (size_t)i * Kc);
    ar[lane]      = xr[lane];
    ar[lane + 32] = xr[lane + 32];
    for (int j = lane; j < STRc; j += 32)        sh[w][j]        = pos[(size_t)i * STRc + j];
    for (int j = lane; j < STRc - 1; j += 32)    sh[w][STRc + j] = lap[(size_t)i * (STRc - 1) + j];
    __syncwarp();
    if (lane < PEc) {
        float acc = bp[lane];
        #pragma unroll 7
        for (int j = 0; j < 2 * STRc - 1; j++) acc += sh[w][j] * Wp[j * PEc + lane];
        g_Abuf[(size_t)i * Kc + Hc + lane] = acc;
    }
}

// ---------------- GEMM: hs0 = norm * (Abuf @ W + b) ----------------
// 128x128 tile, BK=8, 256 threads, 8x8 per thread via f32x2 packed FMA
__global__ __launch_bounds__(256) void k_gemm(const float* __restrict__ W,
                                              const float* __restrict__ bias) {
    __shared__ __align__(16) float As[8][128];
    __shared__ __align__(16) float Bs[8][128];
    int bm = blockIdx.x * 128;
    int bn = blockIdx.y * 128;
    int t = threadIdx.x;
    int arow = t >> 1, acq = (t & 1) * 4;     // A: 128 rows x 8 k, float4 per thread
    int bk = t >> 5,  bnq = (t & 31) * 4;     // B: 8 k x 128 n, float4 per thread
    int tm = (t >> 4) * 8, tn = (t & 15) * 8;

    uint64_t acc[8][4];
    #pragma unroll
    for (int m = 0; m < 8; m++)
        #pragma unroll
        for (int p = 0; p < 4; p++) acc[m][p] = 0ull;

    for (int k0 = 0; k0 < Kc; k0 += 8) {
        float4 av = make_float4(0.f, 0.f, 0.f, 0.f);
        if (bm + arow < Nn)
            av = *(const float4*)(g_Abuf + (size_t)(bm + arow) * Kc + k0 + acq);
        As[acq + 0][arow] = av.x; As[acq + 1][arow] = av.y;
        As[acq + 2][arow] = av.z; As[acq + 3][arow] = av.w;
        *(float4*)&Bs[bk][bnq] = *(const float4*)(W + (size_t)(k0 + bk) * Hc + bn + bnq);
        __syncthreads();
        #pragma unroll
        for (int k = 0; k < 8; k++) {
            uint64_t aa[8], bb[4];
            #pragma unroll
            for (int m = 0; m < 8; m++) aa[m] = pack2_dup(As[k][tm + m]);
            #pragma unroll
            for (int p = 0; p < 4; p++) bb[p] = *(const uint64_t*)&Bs[k][tn + 2 * p];
            #pragma unroll
            for (int m = 0; m < 8; m++)
                #pragma unroll
                for (int p = 0; p < 4; p++) fma2(acc[m][p], aa[m], bb[p]);
        }
        __syncthreads();
    }

    #pragma unroll
    for (int m = 0; m < 8; m++) {
        int r = bm + tm + m;
        if (r < Nn) {
            float nrm = g_norm[r];
            #pragma unroll
            for (int p = 0; p < 4; p++) {
                int cn = bn + tn + 2 * p;
                float2 c = unpack2(acc[m][p]);
                float2 o;
                o.x = nrm * (c.x + bias[cn]);
                o.y = nrm * (c.y + bias[cn + 1]);
                *(float2*)&g_hs[(size_t)r * Hc + cn] = o;
            }
        }
    }
}

// ---------------- SpMM layer ----------------
// hs_in is pre-scaled (norm*h). Computes t = norm*(sum_j hs_in[j] + hs_in[i]),
// out (+)= jk[L]*t, and (if L<2) hs_out = norm*t for the next layer.
// One 64-lane group per node, float4 per lane.
template <int L>
__global__ void k_spmm(float* __restrict__ out, const float* __restrict__ jkp) {
    const float* __restrict__ hin = (L == 1) ? g_hs2 : g_hs;
    float* __restrict__ hout      = (L == 0) ? g_hs2 : g_hs;  // unused for L==2
    int node = blockIdx.x * 4 + (threadIdx.x >> 6);
    int lane = threadIdx.x & 63;
    if (node >= Nn) return;
    int start = g_rowptr[node];
    int dg = g_deg[node];
    const float4* hin4 = (const float4*)hin;
    size_t off = (size_t)node * 64 + lane;
    float4 acc = hin4[off];
    int k = 0;
    for (; k + 4 <= dg; k += 4) {
        int j0 = g_colsorted[start + k];
        int j1 = g_colsorted[start + k + 1];
        int j2 = g_colsorted[start + k + 2];
        int j3 = g_colsorted[start + k + 3];
        float4 v0 = hin4[(size_t)j0 * 64 + lane];
        float4 v1 = hin4[(size_t)j1 * 64 + lane];
        float4 v2 = hin4[(size_t)j2 * 64 + lane];
        float4 v3 = hin4[(size_t)j3 * 64 + lane];
        acc.x += (v0.x + v1.x) + (v2.x + v3.x);
        acc.y += (v0.y + v1.y) + (v2.y + v3.y);
        acc.z += (v0.z + v1.z) + (v2.z + v3.z);
        acc.w += (v0.w + v1.w) + (v2.w + v3.w);
    }
    for (; k < dg; k++) {
        int j = g_colsorted[start + k];
        float4 v = hin4[(size_t)j * 64 + lane];
        acc.x += v.x; acc.y += v.y; acc.z += v.z; acc.w += v.w;
    }
    float nrm = g_norm[node];
    float jw = __ldg(&jkp[L]);
    float4 tv;
    tv.x = nrm * acc.x; tv.y = nrm * acc.y; tv.z = nrm * acc.z; tv.w = nrm * acc.w;

    float4* out4 = (float4*)out;
    if (L == 0) {
        float4 o;
        o.x = jw * tv.x; o.y = jw * tv.y; o.z = jw * tv.z; o.w = jw * tv.w;
        out4[off] = o;
    } else {
        float4 o = out4[off];
        o.x += jw * tv.x; o.y += jw * tv.y; o.z += jw * tv.z; o.w += jw * tv.w;
        out4[off] = o;
    }
    if (L < 2) {
        float4 hs;
        hs.x = nrm * tv.x; hs.y = nrm * tv.y; hs.z = nrm * tv.z; hs.w = nrm * tv.w;
        ((float4*)hout)[off] = hs;
    }
}

// ---------------- launch ----------------
extern "C" void kernel_launch(void* const* d_in, const int* in_sizes, int n_in,
                              void* d_out, int out_size) {
    const float* x   = (const float*)d_in[0];
    const float* pos = (const float*)d_in[1];
    const float* lap = (const float*)d_in[2];
    const float* Wp  = (const float*)d_in[3];
    const float* bp  = (const float*)d_in[4];
    const float* Wx  = (const float*)d_in[5];
    const float* bx  = (const float*)d_in[6];
    const float* jk  = (const float*)d_in[7];
    const int*   row = (const int*)d_in[8];
    const int*   col = (const int*)d_in[9];
    float* out = (float*)d_out;

    k_zero<<<(Nn + 255) / 256, 256>>>();
    k_deg<<<(Ee + 255) / 256, 256>>>(row);
    k_scan1<<<NBLK, 1024>>>();
    k_scan2<<<1, 128>>>();
    k_scan3<<<(Nn + 255) / 256, 256>>>();
    k_scatter<<<(Ee + 255) / 256, 256>>>(row, col);
    k_pe<<<(Nn + 7) / 8, 256>>>(x, pos, lap, Wp, bp);
    dim3 gg((Nn + 127) / 128, Hc / 128);
    k_gemm<<<gg, 256>>>(Wx, bx);
    k_spmm<0><<<(Nn + 3) / 4, 256>>>(out, jk);
    k_spmm<1><<<(Nn + 3) / 4, 256>>>(out, jk);
    k_spmm<2><<<(Nn + 3) / 4, 256>>>(out, jk);
}

// round 3
// speedup vs baseline: 1.0005x; 1.0005x over previous
#include <cuda_runtime.h>
#include <stdint.h>

#define Nn 100000
#define Ee 3200000
#define Hc 256
#define Kc 264          // 256 + 8 (pe)
#define STRc 60
#define PEc 8
#define NBLK 98         // ceil(Nn/1024)

// ---------------- scratch (device globals: no allocation allowed) ----------------
__device__ float g_Abuf[(size_t)Nn * Kc];     // [x | pe] concatenated, row-major
__device__ float g_hs [(size_t)Nn * Hc];      // pre-scaled features (norm * h)
__device__ float g_hs2[(size_t)Nn * Hc];
__device__ float g_norm[Nn];
__device__ int   g_deg[Nn];
__device__ int   g_cursor[Nn];
__device__ int   g_rowptr[Nn + 1];
__device__ int   g_bsum[128];
__device__ int   g_colsorted[Ee];

// ---------------- small helpers: packed f32x2 FMA ----------------
__device__ __forceinline__ uint64_t pack2_dup(float a) {
    uint32_t u = __float_as_uint(a);
    uint64_t r;
    asm("mov.b64 %0, {%1, %1};" : "=l"(r) : "r"(u));
    return r;
}
__device__ __forceinline__ void fma2(uint64_t& d, uint64_t a, uint64_t b) {
    asm("fma.rn.f32x2 %0, %1, %2, %0;" : "+l"(d) : "l"(a), "l"(b));
}
__device__ __forceinline__ float2 unpack2(uint64_t v) {
    uint32_t lo, hi;
    asm("mov.b64 {%0, %1}, %2;" : "=r"(lo), "=r"(hi) : "l"(v));
    float2 r; r.x = __uint_as_float(lo); r.y = __uint_as_float(hi);
    return r;
}

// ---------------- CSR build ----------------
__global__ void k_zero() {
    int i = blockIdx.x * blockDim.x + threadIdx.x;
    if (i < Nn) { g_deg[i] = 0; g_cursor[i] = 0; }
}

__global__ void k_deg(const int* __restrict__ row) {
    int e = blockIdx.x * blockDim.x + threadIdx.x;
    if (e < Ee) atomicAdd(&g_deg[row[e]], 1);
}

// per-block exclusive scan of deg -> rowptr (partial), block totals -> g_bsum, plus norm
__global__ void k_scan1() {
    __shared__ int s[1024];
    int tid = threadIdx.x;
    int gi = blockIdx.x * 1024 + tid;
    int v = (gi < Nn) ? g_deg[gi] : 0;
    s[tid] = v;
    __syncthreads();
    for (int off = 1; off < 1024; off <<= 1) {
        int t = (tid >= off) ? s[tid - off] : 0;
        __syncthreads();
        s[tid] += t;
        __syncthreads();
    }
    if (gi < Nn) {
        g_rowptr[gi] = s[tid] - v;             // exclusive within block
        g_norm[gi]   = rsqrtf(1.0f + (float)v);
    }
    if (tid == 1023) g_bsum[blockIdx.x] = s[1023];
}

__global__ void k_scan2() {
    __shared__ int s[128];
    int tid = threadIdx.x;
    int v = (tid < NBLK) ? g_bsum[tid] : 0;
    s[tid] = v;
    __syncthreads();
    for (int off = 1; off < 128; off <<= 1) {
        int t = (tid >= off) ? s[tid - off] : 0;
        __syncthreads();
        s[tid] += t;
        __syncthreads();
    }
    g_bsum[tid] = s[tid] - v;                  // exclusive block offsets
}

__global__ void k_scan3() {
    int i = blockIdx.x * blockDim.x + threadIdx.x;
    if (i < Nn) g_rowptr[i] += g_bsum[i >> 10];
}

__global__ void k_scatter(const int* __restrict__ row, const int* __restrict__ col) {
    int e = blockIdx.x * blockDim.x + threadIdx.x;
    if (e < Ee) {
        int r = row[e];
        int p = atomicAdd(&g_cursor[r], 1);
        g_colsorted[g_rowptr[r] + p] = col[e];
    }
}

// ---------------- pos-embedding + x copy into Abuf ----------------
// one warp per node: copies x row (64 float4) and computes 8-wide pe
__global__ void k_pe(const float* __restrict__ x, const float* __restrict__ pos,
                     const float* __restrict__ lap, const float* __restrict__ Wp,
                     const float* __restrict__ bp) {
    __shared__ float sh[8][120];
    int w = threadIdx.x >> 5, lane = threadIdx.x & 31;
    int i = blockIdx.x * 8 + w;
    if (i >= Nn) return;
    const float4* xr = (const float4*)(x + (size_t)i * Hc);
    float4* ar = (float4*)(g_Abuf + (size_t)i * Kc);
    ar[lane]      = xr[lane];
    ar[lane + 32] = xr[lane + 32];
    for (int j = lane; j < STRc; j += 32)        sh[w][j]        = pos[(size_t)i * STRc + j];
    for (int j = lane; j < STRc - 1; j += 32)    sh[w][STRc + j] = lap[(size_t)i * (STRc - 1) + j];
    __syncwarp();
    if (lane < PEc) {
        float acc = bp[lane];
        #pragma unroll 7
        for (int j = 0; j < 2 * STRc - 1; j++) acc += sh[w][j] * Wp[j * PEc + lane];
        g_Abuf[(size_t)i * Kc + Hc + lane] = acc;
    }
}

// ---------------- GEMM: hs0 = norm * (Abuf @ W + b) ----------------
// 128x128 tile, BK=8, 256 threads, 8x8 per thread via f32x2 packed FMA
__global__ __launch_bounds__(256) void k_gemm(const float* __restrict__ W,
                                              const float* __restrict__ bias) {
    __shared__ __align__(16) float As[8][128];
    __shared__ __align__(16) float Bs[8][128];
    int bm = blockIdx.x * 128;
    int bn = blockIdx.y * 128;
    int t = threadIdx.x;
    int arow = t >> 1, acq = (t & 1) * 4;     // A: 128 rows x 8 k, float4 per thread
    int bk = t >> 5,  bnq = (t & 31) * 4;     // B: 8 k x 128 n, float4 per thread
    int tm = (t >> 4) * 8, tn = (t & 15) * 8;

    uint64_t acc[8][4];
    #pragma unroll
    for (int m = 0; m < 8; m++)
        #pragma unroll
        for (int p = 0; p < 4; p++) acc[m][p] = 0ull;

    for (int k0 = 0; k0 < Kc; k0 += 8) {
        float4 av = make_float4(0.f, 0.f, 0.f, 0.f);
        if (bm + arow < Nn)
            av = *(const float4*)(g_Abuf + (size_t)(bm + arow) * Kc + k0 + acq);
        As[acq + 0][arow] = av.x; As[acq + 1][arow] = av.y;
        As[acq + 2][arow] = av.z; As[acq + 3][arow] = av.w;
        *(float4*)&Bs[bk][bnq] = *(const float4*)(W + (size_t)(k0 + bk) * Hc + bn + bnq);
        __syncthreads();
        #pragma unroll
        for (int k = 0; k < 8; k++) {
            uint64_t aa[8], bb[4];
            #pragma unroll
            for (int m = 0; m < 8; m++) aa[m] = pack2_dup(As[k][tm + m]);
            #pragma unroll
            for (int p = 0; p < 4; p++) bb[p] = *(const uint64_t*)&Bs[k][tn + 2 * p];
            #pragma unroll
            for (int m = 0; m < 8; m++)
                #pragma unroll
                for (int p = 0; p < 4; p++) fma2(acc[m][p], aa[m], bb[p]);
        }
        __syncthreads();
    }

    #pragma unroll
    for (int m = 0; m < 8; m++) {
        int r = bm + tm + m;
        if (r < Nn) {
            float nrm = g_norm[r];
            #pragma unroll
            for (int p = 0; p < 4; p++) {
                int cn = bn + tn + 2 * p;
                float2 c = unpack2(acc[m][p]);
                float2 o;
                o.x = nrm * (c.x + bias[cn]);
                o.y = nrm * (c.y + bias[cn + 1]);
                *(float2*)&g_hs[(size_t)r * Hc + cn] = o;
            }
        }
    }
}

// ---------------- SpMM layer ----------------
// hs_in is pre-scaled (norm*h). Computes t = norm*(sum_j hs_in[j] + hs_in[i]),
// out (+)= jk[L]*t, and (if L<2) hs_out = norm*t for the next layer.
// One 64-lane group per node, float4 per lane.
template <int L>
__global__ void k_spmm(float* __restrict__ out, const float* __restrict__ jkp) {
    const float* __restrict__ hin = (L == 1) ? g_hs2 : g_hs;
    float* __restrict__ hout      = (L == 0) ? g_hs2 : g_hs;  // unused for L==2
    int node = blockIdx.x * 4 + (threadIdx.x >> 6);
    int lane = threadIdx.x & 63;
    if (node >= Nn) return;
    int start = g_rowptr[node];
    int dg = g_deg[node];
    const float4* hin4 = (const float4*)hin;
    size_t off = (size_t)node * 64 + lane;
    float4 acc = hin4[off];
    int k = 0;
    for (; k + 4 <= dg; k += 4) {
        int j0 = g_colsorted[start + k];
        int j1 = g_colsorted[start + k + 1];
        int j2 = g_colsorted[start + k + 2];
        int j3 = g_colsorted[start + k + 3];
        float4 v0 = hin4[(size_t)j0 * 64 + lane];
        float4 v1 = hin4[(size_t)j1 * 64 + lane];
        float4 v2 = hin4[(size_t)j2 * 64 + lane];
        float4 v3 = hin4[(size_t)j3 * 64 + lane];
        acc.x += (v0.x + v1.x) + (v2.x + v3.x);
        acc.y += (v0.y + v1.y) + (v2.y + v3.y);
        acc.z += (v0.z + v1.z) + (v2.z + v3.z);
        acc.w += (v0.w + v1.w) + (v2.w + v3.w);
    }
    for (; k < dg; k++) {
        int j = g_colsorted[start + k];
        float4 v = hin4[(size_t)j * 64 + lane];
        acc.x += v.x; acc.y += v.y; acc.z += v.z; acc.w += v.w;
    }
    float nrm = g_norm[node];
    float jw = __ldg(&jkp[L]);
    float4 tv;
    tv.x = nrm * acc.x; tv.y = nrm * acc.y; tv.z = nrm * acc.z; tv.w = nrm * acc.w;

    float4* out4 = (float4*)out;
    if (L == 0) {
        float4 o;
        o.x = jw * tv.x; o.y = jw * tv.y; o.z = jw * tv.z; o.w = jw * tv.w;
        out4[off] = o;
    } else {
        float4 o = out4[off];
        o.x += jw * tv.x; o.y += jw * tv.y; o.z += jw * tv.z; o.w += jw * tv.w;
        out4[off] = o;
    }
    if (L < 2) {
        float4 hs;
        hs.x = nrm * tv.x; hs.y = nrm * tv.y; hs.z = nrm * tv.z; hs.w = nrm * tv.w;
        ((float4*)hout)[off] = hs;
    }
}

// ---------------- launch ----------------
extern "C" void kernel_launch(void* const* d_in, const int* in_sizes, int n_in,
                              void* d_out, int out_size) {
    const float* x   = (const float*)d_in[0];
    const float* pos = (const float*)d_in[1];
    const float* lap = (const float*)d_in[2];
    const float* Wp  = (const float*)d_in[3];
    const float* bp  = (const float*)d_in[4];
    const float* Wx  = (const float*)d_in[5];
    const float* bx  = (const float*)d_in[6];
    const float* jk  = (const float*)d_in[7];
    const int*   row = (const int*)d_in[8];
    const int*   col = (const int*)d_in[9];
    float* out = (float*)d_out;

    k_zero<<<(Nn + 255) / 256, 256>>>();
    k_deg<<<(Ee + 255) / 256, 256>>>(row);
    k_scan1<<<NBLK, 1024>>>();
    k_scan2<<<1, 128>>>();
    k_scan3<<<(Nn + 255) / 256, 256>>>();
    k_scatter<<<(Ee + 255) / 256, 256>>>(row, col);
    k_pe<<<(Nn + 7) / 8, 256>>>(x, pos, lap, Wp, bp);
    dim3 gg((Nn + 127) / 128, Hc / 128);
    k_gemm<<<gg, 256>>>(Wx, bx);
    k_spmm<0><<<(Nn + 3) / 4, 256>>>(out, jk);
    k_spmm<1><<<(Nn + 3) / 4, 256>>>(out, jk);
    k_spmm<2><<<(Nn + 3) / 4, 256>>>(out, jk);
}